// round 2
// baseline (speedup 1.0000x reference)
#include <cuda_runtime.h>

// Problem constants
#define B_  32
#define T_  1024
#define I_  512
#define H_  512
#define M_  (B_*T_)          // 32768
#define KD_ 1024             // 2*I
#define ND_ 1024             // 2*H (n<512: f gate, n>=512: z gate)

#define CHUNKS 16
#define CLEN   (T_/CHUNKS)   // 64

// ---------------- scratch (static __device__, allocation-free) ----------------
__device__ float g_wpack[KD_ * ND_];            // [k][n], 4 MB
__device__ float g_bias[ND_];
__device__ float g_raw[(size_t)M_ * ND_];       // 134 MB: raw_f | raw_z per row
__device__ float g_P[CHUNKS * B_ * H_];         // chunk product of f
__device__ float g_S[CHUNKS * B_ * H_];         // chunk local state (init 0)
__device__ float g_carry[CHUNKS * B_ * H_];     // carry-in state per chunk

// ---------------- weight packing ----------------
// Wpack[k][n]: k<512 -> tap0 (applies to x[t-1]), i=k ; k>=512 -> tap1, i=k-512
// n<512 -> Wf[h=n], n>=512 -> Wz[h=n-512].  W layout (H,I,K): h*1024 + i*2 + tap
__global__ void pack_weights(const float* __restrict__ Wz, const float* __restrict__ bz,
                             const float* __restrict__ Wf, const float* __restrict__ bf) {
    int idx = blockIdx.x * blockDim.x + threadIdx.x;
    if (idx >= KD_ * ND_) return;
    int n = idx & (ND_ - 1);
    int k = idx >> 10;
    int tap = k >> 9;
    int i = k & (I_ - 1);
    int h = n & (H_ - 1);
    const float* W = (n < H_) ? Wf : Wz;
    g_wpack[idx] = W[h * (I_ * 2) + i * 2 + tap];
    if (k == 0) g_bias[n] = (n < H_) ? bf[n] : bz[n - H_];
}

// ---------------- SGEMM: raw = A * Wpack + bias ----------------
// A[m,k] = X[m*512 + k - 512], zero when (m % 1024 == 0 && k < 512)
// Block tile 128x128, K-step 8, 256 threads, 8x8 per thread, double-buffered smem.
__global__ __launch_bounds__(256, 2) void gemm_kernel(const float* __restrict__ X) {
    __shared__ float As[2][8][128];
    __shared__ float Bs[2][8][128];

    const int tid = threadIdx.x;
    const int m0 = blockIdx.y * 128;
    const int n0 = blockIdx.x * 128;

    // A-tile load mapping: 128 rows x 8 k, one float4 (4 k's) per thread
    const int a_row = tid >> 1;            // 0..127
    const int a_kk  = (tid & 1) * 4;       // 0 or 4
    const int gm    = m0 + a_row;
    const bool row_t0 = ((gm & (T_ - 1)) == 0);

    // B-tile load mapping: 8 k-rows x 128 n, one float4 per thread
    const int b_kr = tid >> 5;             // 0..7
    const int b_nc = (tid & 31) * 4;       // 0..124

    // compute mapping: 16x16 threads, 8x8 micro-tile
    const int tr = (tid >> 4) * 8;
    const int tc = (tid & 15) * 8;

    float acc[8][8];
    #pragma unroll
    for (int i = 0; i < 8; i++)
        #pragma unroll
        for (int j = 0; j < 8; j++) acc[i][j] = 0.f;

    // prologue: tile 0
    {
        const int k = a_kk;  // k0 = 0, always < 512
        float4 va;
        if (row_t0) va = make_float4(0.f, 0.f, 0.f, 0.f);
        else        va = *(const float4*)(X + gm * I_ + k - I_);
        As[0][a_kk + 0][a_row] = va.x;
        As[0][a_kk + 1][a_row] = va.y;
        As[0][a_kk + 2][a_row] = va.z;
        As[0][a_kk + 3][a_row] = va.w;
        float4 vb = *(const float4*)(g_wpack + b_kr * ND_ + n0 + b_nc);
        *(float4*)&Bs[0][b_kr][b_nc] = vb;
    }
    __syncthreads();

    int buf = 0;
    #pragma unroll 1
    for (int kt = 0; kt < KD_ / 8; kt++) {
        float4 va, vb;
        const int k0n = (kt + 1) * 8;
        if (kt < KD_ / 8 - 1) {
            const int k = k0n + a_kk;
            if (row_t0 && k < I_) va = make_float4(0.f, 0.f, 0.f, 0.f);
            else                  va = *(const float4*)(X + gm * I_ + k - I_);
            vb = *(const float4*)(g_wpack + (k0n + b_kr) * ND_ + n0 + b_nc);
        }
        #pragma unroll
        for (int kk = 0; kk < 8; kk++) {
            float a[8], b[8];
            *(float4*)(a)     = *(const float4*)&As[buf][kk][tr];
            *(float4*)(a + 4) = *(const float4*)&As[buf][kk][tr + 4];
            *(float4*)(b)     = *(const float4*)&Bs[buf][kk][tc];
            *(float4*)(b + 4) = *(const float4*)&Bs[buf][kk][tc + 4];
            #pragma unroll
            for (int i = 0; i < 8; i++)
                #pragma unroll
                for (int j = 0; j < 8; j++)
                    acc[i][j] = fmaf(a[i], b[j], acc[i][j]);
        }
        if (kt < KD_ / 8 - 1) {
            As[buf ^ 1][a_kk + 0][a_row] = va.x;
            As[buf ^ 1][a_kk + 1][a_row] = va.y;
            As[buf ^ 1][a_kk + 2][a_row] = va.z;
            As[buf ^ 1][a_kk + 3][a_row] = va.w;
            *(float4*)&Bs[buf ^ 1][b_kr][b_nc] = vb;
            __syncthreads();
            buf ^= 1;
        }
    }

    // epilogue: + bias, store raw
    #pragma unroll
    for (int i = 0; i < 8; i++) {
        const size_t base = (size_t)(m0 + tr + i) * ND_ + n0 + tc;
        float4 v0, v1;
        v0.x = acc[i][0] + g_bias[n0 + tc + 0];
        v0.y = acc[i][1] + g_bias[n0 + tc + 1];
        v0.z = acc[i][2] + g_bias[n0 + tc + 2];
        v0.w = acc[i][3] + g_bias[n0 + tc + 3];
        v1.x = acc[i][4] + g_bias[n0 + tc + 4];
        v1.y = acc[i][5] + g_bias[n0 + tc + 5];
        v1.z = acc[i][6] + g_bias[n0 + tc + 6];
        v1.w = acc[i][7] + g_bias[n0 + tc + 7];
        *(float4*)(g_raw + base)     = v0;
        *(float4*)(g_raw + base + 4) = v1;
    }
}

// ---------------- scan: h[t] = f*h[t-1] + (1-f)*z ----------------
__device__ __forceinline__ float sigmoidf_(float x) {
    return __fdividef(1.0f, 1.0f + __expf(-x));
}

// phase 1: per-(b,h,chunk) — product of f and local state with zero init
__global__ void scan_p1() {
    const int g = blockIdx.x * blockDim.x + threadIdx.x;  // 262144 threads
    const int h = g & (H_ - 1);
    const int bc = g >> 9;
    const int b = bc & (B_ - 1);
    const int c = bc >> 5;
    const size_t m = (size_t)b * T_ + (size_t)c * CLEN;
    const float* pf = g_raw + m * ND_ + h;
    float s = 0.f, P = 1.f;
    #pragma unroll 4
    for (int t = 0; t < CLEN; t++) {
        float f = sigmoidf_(pf[(size_t)t * ND_]);
        float z = sigmoidf_(pf[(size_t)t * ND_ + H_]);
        s = fmaf(f, s, (1.f - f) * z);
        P *= f;
    }
    const int idx = (c * B_ + b) * H_ + h;
    g_P[idx] = P;
    g_S[idx] = s;
}

// phase 2: per-(b,h) — sequential combine over chunks, record carry-in
__global__ void scan_p2() {
    const int g = blockIdx.x * blockDim.x + threadIdx.x;  // 16384 threads
    const int h = g & (H_ - 1);
    const int b = g >> 9;
    float carry = 0.f;
    #pragma unroll
    for (int c = 0; c < CHUNKS; c++) {
        const int idx = (c * B_ + b) * H_ + h;
        g_carry[idx] = carry;
        carry = fmaf(g_P[idx], carry, g_S[idx]);
    }
}

// phase 3: re-run with carry-in, write hidden
__global__ void scan_p3(float* __restrict__ out) {
    const int g = blockIdx.x * blockDim.x + threadIdx.x;  // 262144 threads
    const int h = g & (H_ - 1);
    const int bc = g >> 9;
    const int b = bc & (B_ - 1);
    const int c = bc >> 5;
    const size_t m = (size_t)b * T_ + (size_t)c * CLEN;
    const float* pf = g_raw + m * ND_ + h;
    float* po = out + m * H_ + h;
    float s = g_carry[(c * B_ + b) * H_ + h];
    #pragma unroll 4
    for (int t = 0; t < CLEN; t++) {
        float f = sigmoidf_(pf[(size_t)t * ND_]);
        float z = sigmoidf_(pf[(size_t)t * ND_ + H_]);
        s = fmaf(f, s, (1.f - f) * z);
        po[(size_t)t * H_] = s;
    }
}

// ---------------- launch ----------------
extern "C" void kernel_launch(void* const* d_in, const int* in_sizes, int n_in,
                              void* d_out, int out_size) {
    const float* inputs = (const float*)d_in[0];
    // d_in[1] = init_state (unused by reference)
    const float* Wz = (const float*)d_in[2];
    const float* bz = (const float*)d_in[3];
    const float* Wf = (const float*)d_in[4];
    const float* bf = (const float*)d_in[5];
    float* out = (float*)d_out;

    pack_weights<<<(KD_ * ND_ + 255) / 256, 256>>>(Wz, bz, Wf, bf);

    dim3 ggrid(ND_ / 128, M_ / 128);  // (8, 256)
    gemm_kernel<<<ggrid, 256>>>(inputs);

    scan_p1<<<(CHUNKS * B_ * H_) / 256, 256>>>();
    scan_p2<<<(B_ * H_) / 256, 256>>>();
    scan_p3<<<(CHUNKS * B_ * H_) / 256, 256>>>(out);
}

// round 4
// speedup vs baseline: 3.6371x; 3.6371x over previous
#include <cuda_runtime.h>
#include <cstdint>

// Problem constants
#define B_  32
#define T_  1024
#define I_  512
#define H_  512
#define M_  (B_*T_)          // 32768
#define KD_ 1024             // 2*I
#define ND_ 1024             // 2*H (n<512: f gate, n>=512: z gate)

#define CHUNKS 16
#define CLEN   (T_/CHUNKS)   // 64

// GEMM tiling
#define BM 128
#define BN 128
#define BK 16
#define STAGES 4
#define STG_A 8192           // 128 rows x 64B
#define STG_BYTES 16384      // A + B per stage
#define NKT (KD_/BK)         // 64 k-steps

// ---------------- scratch (static __device__, allocation-free) ----------------
__device__ __align__(128) float g_bmat[ND_ * KD_];   // [n][k] row-major, tf32-rounded
__device__ float g_bias[ND_];
__device__ float g_raw[(size_t)M_ * ND_];            // 134 MB
__device__ float g_P[CHUNKS * B_ * H_];
__device__ float g_S[CHUNKS * B_ * H_];
__device__ float g_carry[CHUNKS * B_ * H_];

// ================= helpers =================
__device__ __forceinline__ uint32_t smem_u32(const void* p) {
    uint32_t a;
    asm("{ .reg .u64 t; cvta.to.shared.u64 t, %1; cvt.u32.u64 %0, t; }" : "=r"(a) : "l"(p));
    return a;
}
// SW64-style swizzle for 64-byte rows: chunk bits [5:4] ^= row bits [8:7]
__device__ __forceinline__ uint32_t swz(uint32_t off) {
    return off ^ ((off >> 3) & 0x30);
}
__device__ __forceinline__ void cp_async16(uint32_t dst, const void* src, int srcsize) {
    asm volatile("cp.async.cg.shared.global [%0], [%1], 16, %2;"
        :: "r"(dst), "l"(src), "r"(srcsize) : "memory");
}
__device__ __forceinline__ void ldsm_x4(uint32_t* r, uint32_t addr) {
    asm volatile("ldmatrix.sync.aligned.m8n8.x4.shared.b16 {%0,%1,%2,%3}, [%4];"
        : "=r"(r[0]), "=r"(r[1]), "=r"(r[2]), "=r"(r[3]) : "r"(addr));
}
__device__ __forceinline__ void mma_tf32(float* c, const uint32_t* a, uint32_t b0, uint32_t b1) {
    asm volatile(
        "mma.sync.aligned.m16n8k8.row.col.f32.tf32.tf32.f32 "
        "{%0,%1,%2,%3}, {%4,%5,%6,%7}, {%8,%9}, {%0,%1,%2,%3};"
        : "+f"(c[0]), "+f"(c[1]), "+f"(c[2]), "+f"(c[3])
        : "r"(a[0]), "r"(a[1]), "r"(a[2]), "r"(a[3]), "r"(b0), "r"(b1));
}

// ---------------- weight packing: Bmat[n][k], rounded to tf32 ----------------
__global__ void pack_weights(const float* __restrict__ Wz, const float* __restrict__ bz,
                             const float* __restrict__ Wf, const float* __restrict__ bf) {
    int idx = blockIdx.x * blockDim.x + threadIdx.x;
    if (idx >= ND_ * KD_) return;
    int n = idx >> 10;
    int k = idx & (KD_ - 1);
    int tap = k >> 9;          // k<512 -> tap0 (x[t-1]), k>=512 -> tap1 (x[t])
    int i = k & (I_ - 1);
    int h = n & (H_ - 1);
    const float* W = (n < H_) ? Wf : Wz;
    float w = W[h * (I_ * 2) + i * 2 + tap];
    asm("cvt.rna.tf32.f32 %0, %1;" : "=f"(w) : "f"(w));  // unbiased tf32 rounding
    g_bmat[idx] = w;
    if (k == 0) g_bias[n] = (n < H_) ? bf[n] : bz[n - H_];
}

// ---------------- tf32 mma.sync GEMM: raw = A * Bmat^T + bias ----------------
// A[m,k] = X[(m-1)*512 + k]  (contiguous sliding window); zero when m%1024==0 && k<512.
__global__ __launch_bounds__(256) void gemm_tc(const float* __restrict__ X) {
    extern __shared__ char smem_raw[];
    const uint32_t raw_b = smem_u32(smem_raw);
    const uint32_t sbase = (raw_b + 127u) & ~127u;

    const int tid  = threadIdx.x;
    const int lane = tid & 31;
    const int wid  = tid >> 5;
    const int wm   = wid >> 2;       // 0..1 -> 64-row half
    const int wn   = wid & 3;        // 0..3 -> 32-col quarter
    const int n0   = blockIdx.x * BN;
    const int m0   = blockIdx.y * BM;
    const bool seq0 = ((m0 & (T_ - 1)) == 0);

    // ---- global->smem load mapping: 2 A chunks + 2 B chunks per thread ----
    int ld_row[2], ld_c[2];
    uint32_t ld_off[2];
    const float* aSrc[2];
    const float* bSrc[2];
    bool zchunk[2];
    #pragma unroll
    for (int j = 0; j < 2; j++) {
        int cid = tid * 2 + j;
        ld_row[j] = cid >> 2;
        ld_c[j]   = cid & 3;
        ld_off[j] = swz((uint32_t)(ld_row[j] * 64 + ld_c[j] * 16));
        aSrc[j] = X + (ptrdiff_t)(m0 + ld_row[j] - 1) * I_ + ld_c[j] * 4;
        bSrc[j] = g_bmat + (size_t)(n0 + ld_row[j]) * KD_ + ld_c[j] * 4;
        zchunk[j] = seq0 && (ld_row[j] == 0);
    }

    // ---- ldmatrix address params ----
    // A: row = wm*64 + mt*16 + (lane&15), chunk = 2*kh + ((lane>>4)&1)
    const int a_l15 = lane & 15;
    const int a_hi  = (lane >> 4) & 1;
    const uint32_t a_cx = (uint32_t)((a_l15 >> 1) & 3);
    uint32_t a_rowterm[4];
    #pragma unroll
    for (int mt = 0; mt < 4; mt++)
        a_rowterm[mt] = (uint32_t)((wm * 64 + mt * 16 + a_l15) * 64);
    // B: row = wn*32 + p*16 + ((lane>>4)&1)*8 + (lane&7), chunk = 2*kh + ((lane>>3)&1)
    const int b_l7 = lane & 7;
    const int b_hi = (lane >> 3) & 1;
    const uint32_t b_cx = (uint32_t)((b_l7 >> 1) & 3);
    uint32_t b_rowterm[2];
    #pragma unroll
    for (int p = 0; p < 2; p++)
        b_rowterm[p] = (uint32_t)((wn * 32 + p * 16 + ((lane >> 4) & 1) * 8 + b_l7) * 64);

    // ---- bias (per-thread columns) ----
    float2 bias2[4];
    #pragma unroll
    for (int nt = 0; nt < 4; nt++)
        bias2[nt] = *(const float2*)(g_bias + n0 + wn * 32 + nt * 8 + (lane & 3) * 2);

    float acc[4][4][4];
    #pragma unroll
    for (int mt = 0; mt < 4; mt++)
        #pragma unroll
        for (int nt = 0; nt < 4; nt++)
            #pragma unroll
            for (int q = 0; q < 4; q++) acc[mt][nt][q] = 0.f;

    // ---- producer ----
    auto issue = [&](int kt) {
        const uint32_t ab = sbase + (uint32_t)((kt & 3) * STG_BYTES);
        const uint32_t bb = ab + STG_A;
        #pragma unroll
        for (int j = 0; j < 2; j++) {
            const bool zz = zchunk[j] && (kt < 32);   // k = kt*16 + c*4 .. +3 < 512
            cp_async16(ab + ld_off[j], zz ? (const void*)X : (const void*)(aSrc[j] + kt * 16),
                       zz ? 0 : 16);
            cp_async16(bb + ld_off[j], bSrc[j] + kt * 16, 16);
        }
        asm volatile("cp.async.commit_group;" ::: "memory");
    };

    issue(0); issue(1); issue(2);

    #pragma unroll 1
    for (int kt = 0; kt < NKT; kt++) {
        if (kt < NKT - 2)      asm volatile("cp.async.wait_group 2;" ::: "memory");
        else if (kt == NKT - 2) asm volatile("cp.async.wait_group 1;" ::: "memory");
        else                   asm volatile("cp.async.wait_group 0;" ::: "memory");
        __syncthreads();
        if (kt + 3 < NKT) issue(kt + 3);

        const uint32_t ab = sbase + (uint32_t)((kt & 3) * STG_BYTES);
        const uint32_t bb = ab + STG_A;
        #pragma unroll
        for (int kh = 0; kh < 2; kh++) {
            uint32_t afr[4][4], bfr[2][4];
            #pragma unroll
            for (int mt = 0; mt < 4; mt++)
                ldsm_x4(afr[mt], ab + a_rowterm[mt]
                                 + ((((uint32_t)(2 * kh + a_hi)) ^ a_cx) << 4));
            #pragma unroll
            for (int p = 0; p < 2; p++)
                ldsm_x4(bfr[p], bb + b_rowterm[p]
                                 + ((((uint32_t)(2 * kh + b_hi)) ^ b_cx) << 4));
            #pragma unroll
            for (int mt = 0; mt < 4; mt++)
                #pragma unroll
                for (int nt = 0; nt < 4; nt++)
                    mma_tf32(acc[mt][nt], afr[mt],
                             bfr[nt >> 1][(nt & 1) * 2], bfr[nt >> 1][(nt & 1) * 2 + 1]);
        }
    }

    // ---- epilogue: + bias, store raw ----
    #pragma unroll
    for (int mt = 0; mt < 4; mt++) {
        const int r0g = m0 + wm * 64 + mt * 16 + (lane >> 2);
        #pragma unroll
        for (int nt = 0; nt < 4; nt++) {
            const int col = n0 + wn * 32 + nt * 8 + (lane & 3) * 2;
            float2 v0, v1;
            v0.x = acc[mt][nt][0] + bias2[nt].x;
            v0.y = acc[mt][nt][1] + bias2[nt].y;
            v1.x = acc[mt][nt][2] + bias2[nt].x;
            v1.y = acc[mt][nt][3] + bias2[nt].y;
            *(float2*)(g_raw + (size_t)r0g * ND_ + col)       = v0;
            *(float2*)(g_raw + (size_t)(r0g + 8) * ND_ + col) = v1;
        }
    }
}

// ---------------- scan: h[t] = f*h[t-1] + (1-f)*z ----------------
__device__ __forceinline__ float sigmoidf_(float x) {
    return __fdividef(1.0f, 1.0f + __expf(-x));
}

__global__ void scan_p1() {
    const int g = blockIdx.x * blockDim.x + threadIdx.x;
    const int h = g & (H_ - 1);
    const int bc = g >> 9;
    const int b = bc & (B_ - 1);
    const int cch = bc >> 5;
    const size_t m = (size_t)b * T_ + (size_t)cch * CLEN;
    const float* pf = g_raw + m * ND_ + h;
    float s = 0.f, P = 1.f;
    #pragma unroll 4
    for (int t = 0; t < CLEN; t++) {
        float f = sigmoidf_(pf[(size_t)t * ND_]);
        float z = sigmoidf_(pf[(size_t)t * ND_ + H_]);
        s = fmaf(f, s, (1.f - f) * z);
        P *= f;
    }
    const int idx = (cch * B_ + b) * H_ + h;
    g_P[idx] = P;
    g_S[idx] = s;
}

__global__ void scan_p2() {
    const int g = blockIdx.x * blockDim.x + threadIdx.x;
    const int h = g & (H_ - 1);
    const int b = g >> 9;
    float carry = 0.f;
    #pragma unroll
    for (int cch = 0; cch < CHUNKS; cch++) {
        const int idx = (cch * B_ + b) * H_ + h;
        g_carry[idx] = carry;
        carry = fmaf(g_P[idx], carry, g_S[idx]);
    }
}

__global__ void scan_p3(float* __restrict__ out) {
    const int g = blockIdx.x * blockDim.x + threadIdx.x;
    const int h = g & (H_ - 1);
    const int bc = g >> 9;
    const int b = bc & (B_ - 1);
    const int cch = bc >> 5;
    const size_t m = (size_t)b * T_ + (size_t)cch * CLEN;
    const float* pf = g_raw + m * ND_ + h;
    float* po = out + m * H_ + h;
    float s = g_carry[(cch * B_ + b) * H_ + h];
    #pragma unroll 4
    for (int t = 0; t < CLEN; t++) {
        float f = sigmoidf_(pf[(size_t)t * ND_]);
        float z = sigmoidf_(pf[(size_t)t * ND_ + H_]);
        s = fmaf(f, s, (1.f - f) * z);
        po[(size_t)t * H_] = s;
    }
}

// ---------------- launch ----------------
extern "C" void kernel_launch(void* const* d_in, const int* in_sizes, int n_in,
                              void* d_out, int out_size) {
    const float* inputs = (const float*)d_in[0];
    const float* Wz = (const float*)d_in[2];
    const float* bz = (const float*)d_in[3];
    const float* Wf = (const float*)d_in[4];
    const float* bf = (const float*)d_in[5];
    float* out = (float*)d_out;

    pack_weights<<<(ND_ * KD_ + 255) / 256, 256>>>(Wz, bz, Wf, bf);

    const int smem_need = STAGES * STG_BYTES + 128;   // 64 KB + align slack
    cudaFuncSetAttribute(gemm_tc, cudaFuncAttributeMaxDynamicSharedMemorySize, smem_need);
    dim3 ggrid(ND_ / BN, M_ / BM);  // (8, 256)
    gemm_tc<<<ggrid, 256, smem_need>>>(inputs);

    scan_p1<<<(CHUNKS * B_ * H_) / 256, 256>>>();
    scan_p2<<<(B_ * H_) / 256, 256>>>();
    scan_p3<<<(CHUNKS * B_ * H_) / 256, 256>>>(out);
}